// round 3
// baseline (speedup 1.0000x reference)
#include <cuda_runtime.h>
#include <math.h>

#define NQ 20
#define NSTATE (1 << NQ)

// 8 MB state scratch (allowed: __device__ global, no runtime alloc)
__device__ __align__(16) float2 d_state[NSTATE];
__device__ float d_partial[1024];
__device__ float d_mean_val;

struct Gate { float2 a, b, c, d; };

// U3(theta, phi, lam) = [[ct, -e^{i lam} st], [e^{i phi} st, e^{i(phi+lam)} ct]]
__device__ __forceinline__ Gate make_gate(float th, float ph, float la) {
    float st, ct, sl, cl, sp, cp;
    sincosf(0.5f * th, &st, &ct);
    sincosf(la, &sl, &cl);
    sincosf(ph, &sp, &cp);
    Gate g;
    g.a = make_float2(ct, 0.f);
    g.b = make_float2(-cl * st, -sl * st);
    g.c = make_float2(cp * st, sp * st);
    float cpl = cp * cl - sp * sl;
    float spl = sp * cl + cp * sl;
    g.d = make_float2(cpl * ct, spl * ct);
    return g;
}

// Apply 2x2 gate on local bit b of a 4096-element smem tile. 256 threads, 2048 pairs.
__device__ __forceinline__ void apply_u3(float2* tile, int b, Gate g, int tid) {
    int mask = (1 << b) - 1;
#pragma unroll
    for (int it = 0; it < 8; ++it) {
        int p = tid + (it << 8);                 // 0..2047
        int i0 = ((p & ~mask) << 1) | (p & mask);
        int i1 = i0 | (1 << b);
        float2 x0 = tile[i0], x1 = tile[i1];
        float2 n0, n1;
        n0.x = g.a.x * x0.x - g.a.y * x0.y + g.b.x * x1.x - g.b.y * x1.y;
        n0.y = g.a.x * x0.y + g.a.y * x0.x + g.b.x * x1.y + g.b.y * x1.x;
        n1.x = g.c.x * x0.x - g.c.y * x0.y + g.d.x * x1.x - g.d.y * x1.y;
        n1.y = g.c.x * x0.y + g.c.y * x0.x + g.d.x * x1.y + g.d.y * x1.x;
        tile[i0] = n0;
        tile[i1] = n1;
    }
}

// Controlled-U3: control local bit cb, target local bit tb. Only control==1 half. 1024 pairs.
__device__ __forceinline__ void apply_cu3(float2* tile, int cb, int tb, Gate g, int tid) {
    int b1 = cb < tb ? cb : tb;
    int b2 = cb < tb ? tb : cb;
    int m1 = (1 << b1) - 1;
    int m2 = (1 << b2) - 1;
#pragma unroll
    for (int it = 0; it < 4; ++it) {
        int p = tid + (it << 8);                 // 0..1023
        int t1 = ((p & ~m1) << 1) | (p & m1);    // insert 0 at b1
        int i0 = ((t1 & ~m2) << 1) | (t1 & m2);  // insert 0 at b2
        i0 |= (1 << cb);                         // control = 1, target = 0
        int i1 = i0 | (1 << tb);
        float2 x0 = tile[i0], x1 = tile[i1];
        float2 n0, n1;
        n0.x = g.a.x * x0.x - g.a.y * x0.y + g.b.x * x1.x - g.b.y * x1.y;
        n0.y = g.a.x * x0.y + g.a.y * x0.x + g.b.x * x1.y + g.b.y * x1.x;
        n1.x = g.c.x * x0.x - g.c.y * x0.y + g.d.x * x1.x - g.d.y * x1.y;
        n1.y = g.c.x * x0.y + g.c.y * x0.x + g.d.x * x1.y + g.d.y * x1.x;
        tile[i0] = n0;
        tile[i1] = n1;
    }
}

// Kernel A: local qubits (= bits) 0..11, contiguous tile. Gates: U3 q=0..11, CU3 (0,1)..(10,11).
template <bool INIT>
__global__ void __launch_bounds__(256) gate_kernel_A(const float* __restrict__ u3p,
                                                     const float* __restrict__ cu3p, int k) {
    __shared__ __align__(16) float2 tile[4096];
    __shared__ Gate gs[23];
    int tid = threadIdx.x;
    int cta = blockIdx.x;  // bits 12..19

    if (tid < 23) {
        const float* p = (tid < 12) ? (u3p + (k * NQ + tid) * 3)
                                    : (cu3p + (k * NQ + (tid - 12)) * 3);
        gs[tid] = make_gate(p[0], p[1], p[2]);
    }

    float4* t4 = (float4*)tile;
    if (INIT) {
#pragma unroll
        for (int it = 0; it < 8; ++it) t4[tid + (it << 8)] = make_float4(0.f, 0.f, 0.f, 0.f);
        if (cta == 0 && tid == 0) tile[0] = make_float2(1.f, 0.f);  // |0...0>
    } else {
        const float4* g4 = (const float4*)(d_state + ((size_t)cta << 12));
#pragma unroll
        for (int it = 0; it < 8; ++it) t4[tid + (it << 8)] = g4[tid + (it << 8)];
    }
    __syncthreads();

    for (int q = 0; q < 12; ++q) { apply_u3(tile, q, gs[q], tid); __syncthreads(); }
    for (int q = 0; q < 11; ++q) { apply_cu3(tile, q, q + 1, gs[12 + q], tid); __syncthreads(); }

    float4* g4 = (float4*)(d_state + ((size_t)cta << 12));
#pragma unroll
    for (int it = 0; it < 8; ++it) g4[tid + (it << 8)] = t4[tid + (it << 8)];
}

// Kernel B: local bits {0,1,2,11..19}. Local coord l: l0..2 -> bits 0..2, l3..11 -> bits 11..19.
// Gates: U3 q=12..19 (local 4..11), CU3 (11,12)..(18,19) (local (3,4)..(10,11)), CU3 (19,0) (local 11 -> 0).
__global__ void __launch_bounds__(256) gate_kernel_B(const float* __restrict__ u3p,
                                                     const float* __restrict__ cu3p, int k) {
    __shared__ __align__(16) float2 tile[4096];
    __shared__ Gate gs[17];
    int tid = threadIdx.x;
    int cta = blockIdx.x;  // bits 3..10

    if (tid < 17) {
        const float* p = (tid < 8) ? (u3p + (k * NQ + 12 + tid) * 3)
                                   : (cu3p + (k * NQ + 11 + (tid - 8)) * 3);
        gs[tid] = make_gate(p[0], p[1], p[2]);
    }

    int base_mid = cta << 3;
#pragma unroll
    for (int it = 0; it < 16; ++it) {
        int j = tid + (it << 8);
        int g = (j & 7) | base_mid | ((j >> 3) << 11);
        tile[j] = d_state[g];
    }
    __syncthreads();

    for (int q = 0; q < 8; ++q) { apply_u3(tile, 4 + q, gs[q], tid); __syncthreads(); }
    for (int q = 0; q < 8; ++q) { apply_cu3(tile, 3 + q, 4 + q, gs[8 + q], tid); __syncthreads(); }
    apply_cu3(tile, 11, 0, gs[16], tid);
    __syncthreads();

#pragma unroll
    for (int it = 0; it < 16; ++it) {
        int j = tid + (it << 8);
        int g = (j & 7) | base_mid | ((j >> 3) << 11);
        d_state[g] = tile[j];
    }
}

// x[i] = (0.8*tanh(0.1*2^19*|psi|^2))^0.3, written at bit-reversed index; per-CTA partial sums.
__global__ void __launch_bounds__(256) finalize_pass1(float* __restrict__ out) {
    int tid = threadIdx.x;
    int cta = blockIdx.x;  // 1024 CTAs x 1024 elems
    int base = cta << 10;
    float sum = 0.f;
#pragma unroll
    for (int it = 0; it < 4; ++it) {
        int i = base + tid + (it << 8);
        float2 s = d_state[i];
        float pr = s.x * s.x + s.y * s.y;
        float v = 0.8f * tanhf(52428.8f * pr);  // gamma * 2^19 = 52428.8
        float xv = powf(v, 0.3f);
        out[__brev((unsigned)i) >> 12] = xv;    // qubit q -> output bit 19-q
        sum += xv;
    }
    for (int o = 16; o > 0; o >>= 1) sum += __shfl_down_sync(0xffffffffu, sum, o);
    __shared__ float red[8];
    if ((tid & 31) == 0) red[tid >> 5] = sum;
    __syncthreads();
    if (tid == 0) {
        float s = 0.f;
#pragma unroll
        for (int w = 0; w < 8; ++w) s += red[w];
        d_partial[cta] = s;
    }
}

__global__ void __launch_bounds__(256) finalize_pass2() {
    int tid = threadIdx.x;
    float s = d_partial[tid] + d_partial[tid + 256] + d_partial[tid + 512] + d_partial[tid + 768];
    for (int o = 16; o > 0; o >>= 1) s += __shfl_down_sync(0xffffffffu, s, o);
    __shared__ float red[8];
    if ((tid & 31) == 0) red[tid >> 5] = s;
    __syncthreads();
    if (tid == 0) {
        float t = 0.f;
#pragma unroll
        for (int w = 0; w < 8; ++w) t += red[w];
        d_mean_val = t * (1.0f / 1048576.0f);
    }
}

__global__ void __launch_bounds__(256) finalize_pass3(float* __restrict__ out) {
    int i = blockIdx.x * blockDim.x + threadIdx.x;
    out[i] -= d_mean_val;
}

extern "C" void kernel_launch(void* const* d_in, const int* in_sizes, int n_in,
                              void* d_out, int out_size) {
    const float* u3p = (const float*)d_in[0];   // (3, 20, 3) float32
    const float* cu3p = (const float*)d_in[1];  // (3, 20, 3) float32
    float* out = (float*)d_out;                 // 2^20 float32

    gate_kernel_A<true><<<256, 256>>>(u3p, cu3p, 0);
    gate_kernel_B<<<256, 256>>>(u3p, cu3p, 0);
    for (int k = 1; k < 3; ++k) {
        gate_kernel_A<false><<<256, 256>>>(u3p, cu3p, k);
        gate_kernel_B<<<256, 256>>>(u3p, cu3p, k);
    }
    finalize_pass1<<<1024, 256>>>(out);
    finalize_pass2<<<1, 256>>>();
    finalize_pass3<<<4096, 256>>>(out);
}

// round 4
// speedup vs baseline: 1.9822x; 1.9822x over previous
#include <cuda_runtime.h>
#include <math.h>

#define NQ 20
#define NSTATE (1 << NQ)

typedef unsigned long long u64;

__device__ __align__(16) float2 d_state[NSTATE];
__device__ float d_partial[256];
__device__ float d_mean_val;

// ---------- packed f32x2 helpers ----------
__device__ __forceinline__ u64 pack2(float lo, float hi) {
    u64 d; asm("mov.b64 %0,{%1,%2};" : "=l"(d) : "f"(lo), "f"(hi)); return d;
}
__device__ __forceinline__ u64 swp(u64 x) {
    u64 d;
    asm("{\n\t.reg .b32 lo,hi;\n\tmov.b64 {lo,hi}, %1;\n\tmov.b64 %0,{hi,lo};\n\t}"
        : "=l"(d) : "l"(x));
    return d;
}
__device__ __forceinline__ u64 mul2(u64 a, u64 b) {
    u64 d; asm("mul.rn.f32x2 %0,%1,%2;" : "=l"(d) : "l"(a), "l"(b)); return d;
}
__device__ __forceinline__ u64 fma2(u64 a, u64 b, u64 c) {
    u64 d; asm("fma.rn.f32x2 %0,%1,%2,%3;" : "=l"(d) : "l"(a), "l"(b), "l"(c)); return d;
}
__device__ __forceinline__ float2 unp(u64 x) {
    float2 f; asm("mov.b64 {%0,%1}, %2;" : "=f"(f.x), "=f"(f.y) : "l"(x)); return f;
}
__device__ __forceinline__ float tanh_ap(float x) {
    float y; asm("tanh.approx.f32 %0,%1;" : "=f"(y) : "f"(x)); return y;
}

// gate packed layout: [axx, bxx, bxy, cxx, cxy, dxx, dxy] (stride 8 in smem)
// a = (ct,0) real; b = -e^{i la} st; c = e^{i ph} st; d = e^{i(ph+la)} ct
__device__ __forceinline__ void make_gate_packed(const float* p, u64* dst) {
    float st, ct, sl, cl, sp, cp;
    sincosf(0.5f * p[0], &st, &ct);
    sincosf(p[2], &sl, &cl);
    sincosf(p[1], &sp, &cp);
    float bx = -cl * st, by = -sl * st;
    float cx = cp * st, cy = sp * st;
    float cpl = cp * cl - sp * sl, spl = sp * cl + cp * sl;
    float dx = cpl * ct, dy = spl * ct;
    dst[0] = pack2(ct, ct);
    dst[1] = pack2(bx, bx);
    dst[2] = pack2(-by, by);
    dst[3] = pack2(cx, cx);
    dst[4] = pack2(-cy, cy);
    dst[5] = pack2(dx, dx);
    dst[6] = pack2(-dy, dy);
}

// n0 = a*x0 + b*x1 (a real), n1 = c*x0 + d*x1, complex, packed re/im in u64
__device__ __forceinline__ void cpair(const u64* g, u64& x0, u64& x1) {
    u64 x0s = swp(x0), x1s = swp(x1);
    u64 n0 = mul2(g[0], x0);
    n0 = fma2(g[1], x1, n0);
    n0 = fma2(g[2], x1s, n0);
    u64 n1 = mul2(g[3], x0);
    n1 = fma2(g[4], x0s, n1);
    n1 = fma2(g[5], x1, n1);
    n1 = fma2(g[6], x1s, n1);
    x0 = n0; x1 = n1;
}

template <int J>
__device__ __forceinline__ void u3_reg(u64* v, const u64* sgate) {
    u64 g[7];
#pragma unroll
    for (int i = 0; i < 7; i++) g[i] = sgate[i];
#pragma unroll
    for (int p = 0; p < 8; p++) {
        int x = p & ((1 << J) - 1);
        int i0 = ((p ^ x) << 1) | x;
        cpair(g, v[i0], v[i0 | (1 << J)]);
    }
}

template <int C, int T>
__device__ __forceinline__ void cu3_reg(u64* v, const u64* sgate) {
    u64 g[7];
#pragma unroll
    for (int i = 0; i < 7; i++) g[i] = sgate[i];
    constexpr int B1 = (C < T) ? C : T;
    constexpr int B2 = (C < T) ? T : C;
#pragma unroll
    for (int p = 0; p < 4; p++) {
        int x = p & ((1 << B1) - 1);
        int t1 = ((p ^ x) << 1) | x;
        int y = t1 & ((1 << B2) - 1);
        int i0 = (((t1 ^ y) << 1) | y) | (1 << C);
        cpair(g, v[i0], v[i0 | (1 << T)]);
    }
}

// bank-conflict-avoiding swizzle for the 4096-entry u64 tile
__device__ __forceinline__ int sw(int i) { return i ^ ((i >> 4) & 15); }

// ============================================================================
// Kernel A: local bits 0..11 contiguous; CTA = bits 12..19.
// Gates: U3 q0..11 (slots 0..11), CU3 (q,q+1) q=0..10 (slots 12..22).
// Windows: {0-3} -> {3-6} -> {6-9} -> {8-11}; load/store layout r = bits 8..11.
// ============================================================================
template <bool INIT>
__global__ void __launch_bounds__(256) gate_A(const float* __restrict__ u3p,
                                              const float* __restrict__ cu3p, int k) {
    __shared__ u64 tile[4096];
    __shared__ u64 sg[23 * 8];
    int tid = threadIdx.x, cta = blockIdx.x;
    u64* gp = (u64*)d_state + ((size_t)cta << 12);

    if (INIT && cta != 0) {
#pragma unroll
        for (int r = 0; r < 16; r++) gp[(r << 8) | tid] = 0ull;
        return;
    }

    if (tid < 23) {
        const float* p = (tid < 12) ? u3p + (k * NQ + tid) * 3
                                    : cu3p + (k * NQ + (tid - 12)) * 3;
        make_gate_packed(p, sg + tid * 8);
    }

    u64 v[16];
    if (INIT) {
#pragma unroll
        for (int r = 0; r < 16; r++) v[r] = 0ull;
        if (tid == 0) v[0] = pack2(1.f, 0.f);
    } else {
#pragma unroll
        for (int r = 0; r < 16; r++) v[r] = gp[(r << 8) | tid];
    }
    __syncthreads();

    // T1: (r<<8)|t  ->  (t<<4)|r   [window {0,1,2,3}]
#pragma unroll
    for (int r = 0; r < 16; r++) tile[sw((r << 8) | tid)] = v[r];
    __syncthreads();
#pragma unroll
    for (int r = 0; r < 16; r++) v[r] = tile[sw((tid << 4) | r)];
    u3_reg<0>(v, sg + 0 * 8); u3_reg<1>(v, sg + 1 * 8);
    u3_reg<2>(v, sg + 2 * 8); u3_reg<3>(v, sg + 3 * 8);
    cu3_reg<0, 1>(v, sg + 12 * 8); cu3_reg<1, 2>(v, sg + 13 * 8); cu3_reg<2, 3>(v, sg + 14 * 8);

    // T2 -> window {3,4,5,6}
    __syncthreads();
#pragma unroll
    for (int r = 0; r < 16; r++) tile[sw((tid << 4) | r)] = v[r];
    __syncthreads();
#pragma unroll
    for (int r = 0; r < 16; r++) v[r] = tile[sw((tid & 7) | (r << 3) | ((tid >> 3) << 7))];
    u3_reg<1>(v, sg + 4 * 8); u3_reg<2>(v, sg + 5 * 8); u3_reg<3>(v, sg + 6 * 8);
    cu3_reg<0, 1>(v, sg + 15 * 8); cu3_reg<1, 2>(v, sg + 16 * 8); cu3_reg<2, 3>(v, sg + 17 * 8);

    // T3 -> window {6,7,8,9}
    __syncthreads();
#pragma unroll
    for (int r = 0; r < 16; r++) tile[sw((tid & 7) | (r << 3) | ((tid >> 3) << 7))] = v[r];
    __syncthreads();
#pragma unroll
    for (int r = 0; r < 16; r++) v[r] = tile[sw((tid & 63) | (r << 6) | ((tid >> 6) << 10))];
    u3_reg<1>(v, sg + 7 * 8); u3_reg<2>(v, sg + 8 * 8); u3_reg<3>(v, sg + 9 * 8);
    cu3_reg<0, 1>(v, sg + 18 * 8); cu3_reg<1, 2>(v, sg + 19 * 8); cu3_reg<2, 3>(v, sg + 20 * 8);

    // T4 -> window {8,9,10,11}
    __syncthreads();
#pragma unroll
    for (int r = 0; r < 16; r++) tile[sw((tid & 63) | (r << 6) | ((tid >> 6) << 10))] = v[r];
    __syncthreads();
#pragma unroll
    for (int r = 0; r < 16; r++) v[r] = tile[sw(tid | (r << 8))];
    u3_reg<2>(v, sg + 10 * 8); u3_reg<3>(v, sg + 11 * 8);
    cu3_reg<1, 2>(v, sg + 21 * 8); cu3_reg<2, 3>(v, sg + 22 * 8);

    // coalesced store (r = bits 8..11)
#pragma unroll
    for (int r = 0; r < 16; r++) gp[(r << 8) | tid] = v[r];
}

// ============================================================================
// Kernel B: local bits l0..2 = global 0..2, l3..11 = global 11..19; CTA = bits 3..10.
// Gates: U3 q12..19 (slots 0..7), CU3 (11+i,12+i) i=0..7 (slots 8..15), CU3 (19,0) slot 16.
// Windows (l-bits): {3-6} -> {6-9} -> {9,10,11,0}; load layout r = l8..11.
// ============================================================================
template <bool LAST>
__global__ void __launch_bounds__(256) gate_B(const float* __restrict__ u3p,
                                              const float* __restrict__ cu3p, int k,
                                              float* __restrict__ out) {
    __shared__ u64 tile[4096];
    __shared__ u64 sg[17 * 8];
    int tid = threadIdx.x, cta = blockIdx.x;

    if (tid < 17) {
        const float* p;
        if (tid < 8)       p = u3p + (k * NQ + 12 + tid) * 3;
        else if (tid < 16) p = cu3p + (k * NQ + 11 + (tid - 8)) * 3;
        else               p = cu3p + (k * NQ + 19) * 3;
        make_gate_packed(p, sg + tid * 8);
    }

    u64* ds = (u64*)d_state;
    int base = (tid & 7) | (cta << 3) | ((tid >> 3) << 11);
    u64 v[16];
#pragma unroll
    for (int r = 0; r < 16; r++) v[r] = ds[base | (r << 16)];
    __syncthreads();

    // T1: (r<<8)|t -> window {l3..l6}
#pragma unroll
    for (int r = 0; r < 16; r++) tile[sw((r << 8) | tid)] = v[r];
    __syncthreads();
#pragma unroll
    for (int r = 0; r < 16; r++) v[r] = tile[sw((tid & 7) | (r << 3) | ((tid >> 3) << 7))];
    u3_reg<1>(v, sg + 0 * 8); u3_reg<2>(v, sg + 1 * 8); u3_reg<3>(v, sg + 2 * 8);
    cu3_reg<0, 1>(v, sg + 8 * 8); cu3_reg<1, 2>(v, sg + 9 * 8); cu3_reg<2, 3>(v, sg + 10 * 8);

    // T2 -> window {l6..l9}
    __syncthreads();
#pragma unroll
    for (int r = 0; r < 16; r++) tile[sw((tid & 7) | (r << 3) | ((tid >> 3) << 7))] = v[r];
    __syncthreads();
#pragma unroll
    for (int r = 0; r < 16; r++) v[r] = tile[sw((tid & 63) | (r << 6) | ((tid >> 6) << 10))];
    u3_reg<1>(v, sg + 3 * 8); u3_reg<2>(v, sg + 4 * 8); u3_reg<3>(v, sg + 5 * 8);
    cu3_reg<0, 1>(v, sg + 11 * 8); cu3_reg<1, 2>(v, sg + 12 * 8); cu3_reg<2, 3>(v, sg + 13 * 8);

    // T3 -> window {l9,l10,l11,l0}: r0..2 = l9..11, r3 = l0; t = l1..l8
    __syncthreads();
#pragma unroll
    for (int r = 0; r < 16; r++) tile[sw((tid & 63) | (r << 6) | ((tid >> 6) << 10))] = v[r];
    __syncthreads();
#pragma unroll
    for (int r = 0; r < 16; r++) v[r] = tile[sw((r >> 3) | (tid << 1) | ((r & 7) << 9))];
    u3_reg<1>(v, sg + 6 * 8); u3_reg<2>(v, sg + 7 * 8);
    cu3_reg<0, 1>(v, sg + 14 * 8); cu3_reg<1, 2>(v, sg + 15 * 8); cu3_reg<2, 3>(v, sg + 16 * 8);

    if (!LAST) {
        // paired store: v[r] (l0=0) and v[r|8] (l0=1) are memory-adjacent -> 16B stores
#pragma unroll
        for (int r = 0; r < 8; r++) {
            int g = ((tid & 3) << 1) | (cta << 3) | (((tid >> 2) | (r << 6)) << 11);
            ulonglong2 val; val.x = v[r]; val.y = v[r | 8];
            *reinterpret_cast<ulonglong2*>(ds + g) = val;
        }
    } else {
        // fused finalize pass1: xv = (0.8*tanh(0.1*2^19*|psi|^2))^0.3 at bit-reversed index
        float sum = 0.f;
#pragma unroll
        for (int h = 0; h < 2; h++) {
            float xv[8];
#pragma unroll
            for (int rr = 0; rr < 8; rr++) {
                float2 a = unp(v[rr | (h << 3)]);
                float pr = a.x * a.x + a.y * a.y;
                float t = 0.8f * tanh_ap(52428.8f * pr);
                float x = __powf(t, 0.3f);
                int j = ((rr & 1) << 2) | (rr & 2) | (rr >> 2);  // brev3
                xv[j] = x;
                sum += x;
            }
            int g0 = h | ((tid & 3) << 1) | (cta << 3) | ((tid >> 2) << 11);
            int obase = (int)(__brev((unsigned)g0) >> 12);  // low 3 bits zero
            float4* o4 = (float4*)(out + obase);
            o4[0] = make_float4(xv[0], xv[1], xv[2], xv[3]);
            o4[1] = make_float4(xv[4], xv[5], xv[6], xv[7]);
        }
        // CTA reduction of partial sum
        for (int o = 16; o > 0; o >>= 1) sum += __shfl_down_sync(0xffffffffu, sum, o);
        __shared__ float red[8];
        if ((tid & 31) == 0) red[tid >> 5] = sum;
        __syncthreads();
        if (tid == 0) {
            float s = 0.f;
#pragma unroll
            for (int w = 0; w < 8; w++) s += red[w];
            d_partial[cta] = s;
        }
    }
}

__global__ void __launch_bounds__(256) finalize_mean() {
    int tid = threadIdx.x;
    float s = d_partial[tid];
    for (int o = 16; o > 0; o >>= 1) s += __shfl_down_sync(0xffffffffu, s, o);
    __shared__ float red[8];
    if ((tid & 31) == 0) red[tid >> 5] = s;
    __syncthreads();
    if (tid == 0) {
        float t = 0.f;
#pragma unroll
        for (int w = 0; w < 8; w++) t += red[w];
        d_mean_val = t * (1.0f / 1048576.0f);
    }
}

__global__ void __launch_bounds__(256) finalize_sub(float4* __restrict__ o4) {
    int i = blockIdx.x * blockDim.x + threadIdx.x;
    float m = d_mean_val;
    float4 x = o4[i];
    x.x -= m; x.y -= m; x.z -= m; x.w -= m;
    o4[i] = x;
}

extern "C" void kernel_launch(void* const* d_in, const int* in_sizes, int n_in,
                              void* d_out, int out_size) {
    const float* u3p = (const float*)d_in[0];   // (3, 20, 3)
    const float* cu3p = (const float*)d_in[1];  // (3, 20, 3)
    float* out = (float*)d_out;                 // 2^20 floats

    gate_A<true><<<256, 256>>>(u3p, cu3p, 0);
    gate_B<false><<<256, 256>>>(u3p, cu3p, 0, out);
    gate_A<false><<<256, 256>>>(u3p, cu3p, 1);
    gate_B<false><<<256, 256>>>(u3p, cu3p, 1, out);
    gate_A<false><<<256, 256>>>(u3p, cu3p, 2);
    gate_B<true><<<256, 256>>>(u3p, cu3p, 2, out);
    finalize_mean<<<1, 256>>>();
    finalize_sub<<<1024, 256>>>((float4*)out);
}

// round 5
// speedup vs baseline: 2.0072x; 1.0126x over previous
#include <cuda_runtime.h>
#include <math.h>

#define NQ 20
#define NSTATE (1 << NQ)

typedef unsigned long long u64;

__device__ __align__(16) float2 d_state[NSTATE];
__device__ float d_partial[256];

// ---------- packed f32x2 helpers ----------
__device__ __forceinline__ u64 pack2(float lo, float hi) {
    u64 d; asm("mov.b64 %0,{%1,%2};" : "=l"(d) : "f"(lo), "f"(hi)); return d;
}
__device__ __forceinline__ u64 swp(u64 x) {
    u64 d;
    asm("{\n\t.reg .b32 lo,hi;\n\tmov.b64 {lo,hi}, %1;\n\tmov.b64 %0,{hi,lo};\n\t}"
        : "=l"(d) : "l"(x));
    return d;
}
__device__ __forceinline__ u64 mul2(u64 a, u64 b) {
    u64 d; asm("mul.rn.f32x2 %0,%1,%2;" : "=l"(d) : "l"(a), "l"(b)); return d;
}
__device__ __forceinline__ u64 fma2(u64 a, u64 b, u64 c) {
    u64 d; asm("fma.rn.f32x2 %0,%1,%2,%3;" : "=l"(d) : "l"(a), "l"(b), "l"(c)); return d;
}
__device__ __forceinline__ float2 unp(u64 x) {
    float2 f; asm("mov.b64 {%0,%1}, %2;" : "=f"(f.x), "=f"(f.y) : "l"(x)); return f;
}
__device__ __forceinline__ float tanh_ap(float x) {
    float y; asm("tanh.approx.f32 %0,%1;" : "=f"(y) : "f"(x)); return y;
}

// gate packed layout: [axx, bxx, bxy, cxx, cxy, dxx, dxy] (stride 8 in smem)
__device__ __forceinline__ void make_gate_packed(const float* p, u64* dst) {
    float st, ct, sl, cl, sp, cp;
    sincosf(0.5f * p[0], &st, &ct);
    sincosf(p[2], &sl, &cl);
    sincosf(p[1], &sp, &cp);
    float bx = -cl * st, by = -sl * st;
    float cx = cp * st, cy = sp * st;
    float cpl = cp * cl - sp * sl, spl = sp * cl + cp * sl;
    float dx = cpl * ct, dy = spl * ct;
    dst[0] = pack2(ct, ct);
    dst[1] = pack2(bx, bx);
    dst[2] = pack2(-by, by);
    dst[3] = pack2(cx, cx);
    dst[4] = pack2(-cy, cy);
    dst[5] = pack2(dx, dx);
    dst[6] = pack2(-dy, dy);
}

// n0 = a*x0 + b*x1 (a real), n1 = c*x0 + d*x1, complex, packed re/im in u64
__device__ __forceinline__ void cpair(const u64* g, u64& x0, u64& x1) {
    u64 x0s = swp(x0), x1s = swp(x1);
    u64 n0 = mul2(g[0], x0);
    n0 = fma2(g[1], x1, n0);
    n0 = fma2(g[2], x1s, n0);
    u64 n1 = mul2(g[3], x0);
    n1 = fma2(g[4], x0s, n1);
    n1 = fma2(g[5], x1, n1);
    n1 = fma2(g[6], x1s, n1);
    x0 = n0; x1 = n1;
}

template <int J>
__device__ __forceinline__ void u3_reg(u64* v, const u64* sgate) {
    u64 g[7];
#pragma unroll
    for (int i = 0; i < 7; i++) g[i] = sgate[i];
#pragma unroll
    for (int p = 0; p < 8; p++) {
        int x = p & ((1 << J) - 1);
        int i0 = ((p ^ x) << 1) | x;
        cpair(g, v[i0], v[i0 | (1 << J)]);
    }
}

template <int C, int T>
__device__ __forceinline__ void cu3_reg(u64* v, const u64* sgate) {
    u64 g[7];
#pragma unroll
    for (int i = 0; i < 7; i++) g[i] = sgate[i];
    constexpr int B1 = (C < T) ? C : T;
    constexpr int B2 = (C < T) ? T : C;
#pragma unroll
    for (int p = 0; p < 4; p++) {
        int x = p & ((1 << B1) - 1);
        int t1 = ((p ^ x) << 1) | x;
        int y = t1 & ((1 << B2) - 1);
        int i0 = (((t1 ^ y) << 1) | y) | (1 << C);
        cpair(g, v[i0], v[i0 | (1 << T)]);
    }
}

// bank-conflict-avoiding swizzle for the 4096-entry u64 tile
__device__ __forceinline__ int sw(int i) { return i ^ ((i >> 4) & 15); }

// ============================================================================
// A body: v enters in window-1 layout (v[r]: local bits 0..3 = r, 4..11 = tid),
// applies U3 q0..11 (sg slots 0..11) + CU3 (0,1)..(10,11) (slots 12..22),
// exits in window-4 layout (v[r]: local bits 8..11 = r, 0..7 = tid).
// ============================================================================
__device__ __forceinline__ void A_body(u64* v, u64* tile, const u64* sg, int tid) {
    // window {0,1,2,3}
    u3_reg<0>(v, sg + 0 * 8); u3_reg<1>(v, sg + 1 * 8);
    u3_reg<2>(v, sg + 2 * 8); u3_reg<3>(v, sg + 3 * 8);
    cu3_reg<0, 1>(v, sg + 12 * 8); cu3_reg<1, 2>(v, sg + 13 * 8); cu3_reg<2, 3>(v, sg + 14 * 8);

    // T2 -> window {3,4,5,6}   (tile's first use in this body: no pre-sync needed)
#pragma unroll
    for (int r = 0; r < 16; r++) tile[sw((tid << 4) | r)] = v[r];
    __syncthreads();
#pragma unroll
    for (int r = 0; r < 16; r++) v[r] = tile[sw((tid & 7) | (r << 3) | ((tid >> 3) << 7))];
    u3_reg<1>(v, sg + 4 * 8); u3_reg<2>(v, sg + 5 * 8); u3_reg<3>(v, sg + 6 * 8);
    cu3_reg<0, 1>(v, sg + 15 * 8); cu3_reg<1, 2>(v, sg + 16 * 8); cu3_reg<2, 3>(v, sg + 17 * 8);

    // T3 -> window {6,7,8,9}
    __syncthreads();
#pragma unroll
    for (int r = 0; r < 16; r++) tile[sw((tid & 7) | (r << 3) | ((tid >> 3) << 7))] = v[r];
    __syncthreads();
#pragma unroll
    for (int r = 0; r < 16; r++) v[r] = tile[sw((tid & 63) | (r << 6) | ((tid >> 6) << 10))];
    u3_reg<1>(v, sg + 7 * 8); u3_reg<2>(v, sg + 8 * 8); u3_reg<3>(v, sg + 9 * 8);
    cu3_reg<0, 1>(v, sg + 18 * 8); cu3_reg<1, 2>(v, sg + 19 * 8); cu3_reg<2, 3>(v, sg + 20 * 8);

    // T4 -> window {8,9,10,11}
    __syncthreads();
#pragma unroll
    for (int r = 0; r < 16; r++) tile[sw((tid & 63) | (r << 6) | ((tid >> 6) << 10))] = v[r];
    __syncthreads();
#pragma unroll
    for (int r = 0; r < 16; r++) v[r] = tile[sw(tid | (r << 8))];
    u3_reg<2>(v, sg + 10 * 8); u3_reg<3>(v, sg + 11 * 8);
    cu3_reg<1, 2>(v, sg + 21 * 8); cu3_reg<2, 3>(v, sg + 22 * 8);
}

// ============================================================================
// B body: local bits l0..2 = g0..2, l3..11 = g11..19; cta = g3..10.
// v enters in window-1 layout (v[r]: l3..6 = r, l0..2 = tid&7, l7..11 = tid>>3).
// Gates: U3 q12..19 (slots 0..7), CU3 (11+i,12+i) (slots 8..15), CU3 (19,0) slot 16.
// Exits in window-3 layout: l0 = r>>3, l1..8 = tid, l9..11 = r&7.
// ============================================================================
__device__ __forceinline__ void B_body(u64* v, u64* tile, const u64* sg, int tid) {
    // window {l3..l6}
    u3_reg<1>(v, sg + 0 * 8); u3_reg<2>(v, sg + 1 * 8); u3_reg<3>(v, sg + 2 * 8);
    cu3_reg<0, 1>(v, sg + 8 * 8); cu3_reg<1, 2>(v, sg + 9 * 8); cu3_reg<2, 3>(v, sg + 10 * 8);

    // T2 -> window {l6..l9}  (pre-sync: tile may have pending readers in the merged kernel)
    __syncthreads();
#pragma unroll
    for (int r = 0; r < 16; r++) tile[sw((tid & 7) | (r << 3) | ((tid >> 3) << 7))] = v[r];
    __syncthreads();
#pragma unroll
    for (int r = 0; r < 16; r++) v[r] = tile[sw((tid & 63) | (r << 6) | ((tid >> 6) << 10))];
    u3_reg<1>(v, sg + 3 * 8); u3_reg<2>(v, sg + 4 * 8); u3_reg<3>(v, sg + 5 * 8);
    cu3_reg<0, 1>(v, sg + 11 * 8); cu3_reg<1, 2>(v, sg + 12 * 8); cu3_reg<2, 3>(v, sg + 13 * 8);

    // T3 -> window {l9,l10,l11,l0}
    __syncthreads();
#pragma unroll
    for (int r = 0; r < 16; r++) tile[sw((tid & 63) | (r << 6) | ((tid >> 6) << 10))] = v[r];
    __syncthreads();
#pragma unroll
    for (int r = 0; r < 16; r++) v[r] = tile[sw((r >> 3) | (tid << 1) | ((r & 7) << 9))];
    u3_reg<1>(v, sg + 6 * 8); u3_reg<2>(v, sg + 7 * 8);
    cu3_reg<0, 1>(v, sg + 14 * 8); cu3_reg<1, 2>(v, sg + 15 * 8); cu3_reg<2, 3>(v, sg + 16 * 8);
}

// B final store for intermediate blocks: v[r]/v[r|8] adjacent in memory -> 16B stores
__device__ __forceinline__ void B_store(const u64* v, u64* ds, int tid, int cta) {
#pragma unroll
    for (int r = 0; r < 8; r++) {
        int g = ((tid & 3) << 1) | (cta << 3) | (((tid >> 2) | (r << 6)) << 11);
        ulonglong2 val; val.x = v[r]; val.y = v[r | 8];
        *reinterpret_cast<ulonglong2*>(ds + g) = val;
    }
}

// ============================================================================
// Fused A(k=0)+B(k=0): after A(0) only 4096 amps (bits g0..11, g12..19=0) are
// nonzero. Every CTA redundantly computes that tile from |0..0>, extracts its
// 16 needed amps, then runs the B(0) gates. No 8MB zero-fill / round trip.
// ============================================================================
__global__ void __launch_bounds__(256) gate_AB0(const float* __restrict__ u3p,
                                                const float* __restrict__ cu3p) {
    __shared__ u64 tile[4096];
    __shared__ u64 sg[40 * 8];
    int tid = threadIdx.x, cta = blockIdx.x;

    if (tid < 40) {
        const float* p;
        if (tid < 12)      p = u3p + tid * 3;                 // A: U3 q0..11
        else if (tid < 23) p = cu3p + (tid - 12) * 3;         // A: CU3 (q,q+1) q=0..10
        else {
            int t = tid - 23;
            if (t < 8)       p = u3p + (12 + t) * 3;          // B: U3 q12..19
            else if (t < 16) p = cu3p + (11 + (t - 8)) * 3;   // B: CU3 (11+i,12+i)
            else             p = cu3p + 19 * 3;               // B: CU3 (19,0)
        }
        make_gate_packed(p, sg + tid * 8);
    }

    u64 v[16];
#pragma unroll
    for (int r = 0; r < 16; r++) v[r] = 0ull;
    if (tid == 0) v[0] = pack2(1.f, 0.f);  // |0...0> in window-1 layout
    __syncthreads();

    A_body(v, tile, sg, tid);

    // publish A tile (window-4 layout -> canonical local index g0..11)
    __syncthreads();
#pragma unroll
    for (int r = 0; r < 16; r++) tile[sw((r << 8) | tid)] = v[r];
    __syncthreads();

    // extract B window-1 inputs: g0..2 = tid (tid<8), g3..10 = cta, g11 = r bit0
    u64 a0 = 0ull, a1 = 0ull;
    if (tid < 8) {
        int i0 = tid | (cta << 3);
        a0 = tile[sw(i0)];
        a1 = tile[sw(i0 | 2048)];
    }
#pragma unroll
    for (int r = 0; r < 16; r++) v[r] = 0ull;
    v[0] = a0; v[1] = a1;

    B_body(v, tile, sg + 23 * 8, tid);
    B_store(v, (u64*)d_state, tid, cta);
}

// ============================================================================
// Kernel A (k=1,2): direct window-1 load (128B contiguous per thread).
// ============================================================================
__global__ void __launch_bounds__(256) gate_A(const float* __restrict__ u3p,
                                              const float* __restrict__ cu3p, int k) {
    __shared__ u64 tile[4096];
    __shared__ u64 sg[23 * 8];
    int tid = threadIdx.x, cta = blockIdx.x;
    u64* gp = (u64*)d_state + ((size_t)cta << 12);

    if (tid < 23) {
        const float* p = (tid < 12) ? u3p + (k * NQ + tid) * 3
                                    : cu3p + (k * NQ + (tid - 12)) * 3;
        make_gate_packed(p, sg + tid * 8);
    }

    u64 v[16];
    const ulonglong2* g2 = (const ulonglong2*)gp;
#pragma unroll
    for (int j = 0; j < 8; j++) {  // v[r] = gp[(tid<<4)|r]
        ulonglong2 val = g2[tid * 8 + j];
        v[2 * j] = val.x; v[2 * j + 1] = val.y;
    }
    __syncthreads();

    A_body(v, tile, sg, tid);

    // coalesced store in window-4 layout
#pragma unroll
    for (int r = 0; r < 16; r++) gp[(r << 8) | tid] = v[r];
}

// ============================================================================
// Kernel B (k=1,2): direct window-1 load. LAST fuses the pointwise finalize.
// ============================================================================
template <bool LAST>
__global__ void __launch_bounds__(256) gate_B(const float* __restrict__ u3p,
                                              const float* __restrict__ cu3p, int k,
                                              float* __restrict__ out) {
    __shared__ u64 tile[4096];
    __shared__ u64 sg[17 * 8];
    int tid = threadIdx.x, cta = blockIdx.x;

    if (tid < 17) {
        const float* p;
        if (tid < 8)       p = u3p + (k * NQ + 12 + tid) * 3;
        else if (tid < 16) p = cu3p + (k * NQ + 11 + (tid - 8)) * 3;
        else               p = cu3p + (k * NQ + 19) * 3;
        make_gate_packed(p, sg + tid * 8);
    }

    u64* ds = (u64*)d_state;
    int b0 = (tid & 7) | (cta << 3) | ((tid >> 3) << 15);
    u64 v[16];
#pragma unroll
    for (int r = 0; r < 16; r++) v[r] = ds[b0 | (r << 11)];  // l3..6 = g11..14 = r
    __syncthreads();

    B_body(v, tile, sg, tid);

    if (!LAST) {
        B_store(v, ds, tid, cta);
    } else {
        // fused finalize: xv = (0.8*tanh(0.1*2^19*|psi|^2))^0.3 at bit-reversed index
        float sum = 0.f;
#pragma unroll
        for (int h = 0; h < 2; h++) {
            float xv[8];
#pragma unroll
            for (int rr = 0; rr < 8; rr++) {
                float2 a = unp(v[rr | (h << 3)]);
                float pr = a.x * a.x + a.y * a.y;
                float t = 0.8f * tanh_ap(52428.8f * pr);
                float x = __powf(t, 0.3f);
                int j = ((rr & 1) << 2) | (rr & 2) | (rr >> 2);  // brev3
                xv[j] = x;
                sum += x;
            }
            int g0 = h | ((tid & 3) << 1) | (cta << 3) | ((tid >> 2) << 11);
            int obase = (int)(__brev((unsigned)g0) >> 12);  // low 3 bits zero
            float4* o4 = (float4*)(out + obase);
            o4[0] = make_float4(xv[0], xv[1], xv[2], xv[3]);
            o4[1] = make_float4(xv[4], xv[5], xv[6], xv[7]);
        }
        for (int o = 16; o > 0; o >>= 1) sum += __shfl_down_sync(0xffffffffu, sum, o);
        __shared__ float red[8];
        if ((tid & 31) == 0) red[tid >> 5] = sum;
        __syncthreads();
        if (tid == 0) {
            float s = 0.f;
#pragma unroll
            for (int w = 0; w < 8; w++) s += red[w];
            d_partial[cta] = s;
        }
    }
}

// mean computed redundantly per CTA from the 256 partials (L2-hot), then subtract
__global__ void __launch_bounds__(256) finalize_sub(float4* __restrict__ o4) {
    int tid = threadIdx.x;
    int i = blockIdx.x * 256 + tid;
    float4 x = o4[i];  // issue early, overlap with reduction

    float s = d_partial[tid];
    for (int o = 16; o > 0; o >>= 1) s += __shfl_down_sync(0xffffffffu, s, o);
    __shared__ float red[8];
    __shared__ float mean;
    if ((tid & 31) == 0) red[tid >> 5] = s;
    __syncthreads();
    if (tid == 0) {
        float t = 0.f;
#pragma unroll
        for (int w = 0; w < 8; w++) t += red[w];
        mean = t * (1.0f / 1048576.0f);
    }
    __syncthreads();
    float m = mean;
    x.x -= m; x.y -= m; x.z -= m; x.w -= m;
    o4[i] = x;
}

extern "C" void kernel_launch(void* const* d_in, const int* in_sizes, int n_in,
                              void* d_out, int out_size) {
    const float* u3p = (const float*)d_in[0];   // (3, 20, 3)
    const float* cu3p = (const float*)d_in[1];  // (3, 20, 3)
    float* out = (float*)d_out;                 // 2^20 floats

    gate_AB0<<<256, 256>>>(u3p, cu3p);
    gate_A<<<256, 256>>>(u3p, cu3p, 1);
    gate_B<false><<<256, 256>>>(u3p, cu3p, 1, out);
    gate_A<<<256, 256>>>(u3p, cu3p, 2);
    gate_B<true><<<256, 256>>>(u3p, cu3p, 2, out);
    finalize_sub<<<1024, 256>>>((float4*)out);
}